// round 1
// baseline (speedup 1.0000x reference)
#include <cuda_runtime.h>

#define NB   2
#define NN   8192
#define NK   16
#define NH   4
#define ND   32
#define HD   128
#define CIN  64
#define COUT 128
#define NPTS (NB * NN)   // 16384

// ---------------- scratch (device globals; no allocations allowed) ----------
__device__ float g_WqA1[CIN * HD];
__device__ float g_WkA1[CIN * HD];
__device__ float g_P2A1[3 * HD];
__device__ float g_c1[HD];
__device__ float g_QA[NPTS * HD];
__device__ float g_KA[NPTS * HD];
__device__ float g_V[NPTS * HD];
__device__ float g_fused[NPTS * HD];

// ---------------- weight folding -------------------------------------------
// blocks 0..63   : rows of WqA1 = Wq @ A1
// blocks 64..127 : rows of WkA1 = Wk @ A1
// block 128      : P2A1 = P2 @ A1   (3 rows)
// block 129      : c1 = b1 + bp2 @ A1
__global__ void setup_kernel(const float* __restrict__ Wq, const float* __restrict__ Wk,
                             const float* __restrict__ A1, const float* __restrict__ P2,
                             const float* __restrict__ b1, const float* __restrict__ bp2) {
    int c   = threadIdx.x;   // 0..127
    int blk = blockIdx.x;
    if (blk < CIN) {
        const float* w = Wq + blk * HD;
        float acc = 0.f;
        for (int j = 0; j < HD; j++) acc = fmaf(w[j], A1[j * HD + c], acc);
        g_WqA1[blk * HD + c] = acc;
    } else if (blk < 2 * CIN) {
        int r = blk - CIN;
        const float* w = Wk + r * HD;
        float acc = 0.f;
        for (int j = 0; j < HD; j++) acc = fmaf(w[j], A1[j * HD + c], acc);
        g_WkA1[r * HD + c] = acc;
    } else if (blk == 2 * CIN) {
        for (int r = 0; r < 3; r++) {
            float acc = 0.f;
            for (int j = 0; j < HD; j++) acc = fmaf(P2[r * HD + j], A1[j * HD + c], acc);
            g_P2A1[r * HD + c] = acc;
        }
    } else {
        float acc = b1[c];
        for (int j = 0; j < HD; j++) acc = fmaf(bp2[j], A1[j * HD + c], acc);
        g_c1[c] = acc;
    }
}

// ---------------- tiled fp32 GEMM:  C[M x 128] = A[M x KD] @ W[KD x 128] (+bias)
// block = 256 threads, tile 64 rows x 128 cols, K chunked by 64.
template <int KD>
__global__ void __launch_bounds__(256) gemm_kernel(const float* __restrict__ A,
                                                   const float* __restrict__ W,
                                                   const float* __restrict__ bias,
                                                   float* __restrict__ C) {
    __shared__ float As[64][64];   // A chunk  (rows x k)
    __shared__ float Bs[64][HD];   // W chunk  (k x cols)

    const int tid  = threadIdx.x;
    const int ty   = tid >> 4;       // 0..15  -> 4 rows each
    const int tx   = tid & 15;       // 0..15  -> 8 cols each
    const int row0 = blockIdx.x * 64;

    float acc[4][8];
#pragma unroll
    for (int i = 0; i < 4; i++)
#pragma unroll
        for (int j = 0; j < 8; j++) acc[i][j] = 0.f;

    for (int kk = 0; kk < KD; kk += 64) {
        if (kk) __syncthreads();
        // load A chunk: 64 rows x 64 floats (coalesced float4)
#pragma unroll
        for (int i = tid; i < 64 * 16; i += 256) {
            int p = i >> 4, q = i & 15;
            float4 v = *(const float4*)(A + (size_t)(row0 + p) * KD + kk + q * 4);
            *(float4*)&As[p][q * 4] = v;
        }
        // load W chunk: 64 x 128 (contiguous block starting at kk*128)
#pragma unroll
        for (int i = tid; i < 64 * 32; i += 256) {
            int j = i >> 5, q = i & 31;
            *(float4*)&Bs[j][q * 4] = *(const float4*)(W + (size_t)(kk + j) * HD + q * 4);
        }
        __syncthreads();

#pragma unroll
        for (int j = 0; j < 64; j++) {
            float a0 = As[ty * 4 + 0][j];
            float a1 = As[ty * 4 + 1][j];
            float a2 = As[ty * 4 + 2][j];
            float a3 = As[ty * 4 + 3][j];
            float4 b0 = *(float4*)&Bs[j][tx * 8];
            float4 b1v = *(float4*)&Bs[j][tx * 8 + 4];
            float bb[8] = {b0.x, b0.y, b0.z, b0.w, b1v.x, b1v.y, b1v.z, b1v.w};
#pragma unroll
            for (int q = 0; q < 8; q++) {
                acc[0][q] = fmaf(a0, bb[q], acc[0][q]);
                acc[1][q] = fmaf(a1, bb[q], acc[1][q]);
                acc[2][q] = fmaf(a2, bb[q], acc[2][q]);
                acc[3][q] = fmaf(a3, bb[q], acc[3][q]);
            }
        }
    }

#pragma unroll
    for (int i = 0; i < 4; i++) {
        float* crow = C + (size_t)(row0 + ty * 4 + i) * HD + tx * 8;
        float o[8];
#pragma unroll
        for (int q = 0; q < 8; q++) {
            o[q] = acc[i][q];
            if (bias) o[q] += bias[tx * 8 + q];
        }
        *(float4*)(crow)     = make_float4(o[0], o[1], o[2], o[3]);
        *(float4*)(crow + 4) = make_float4(o[4], o[5], o[6], o[7]);
    }
}

// ---------------- fused attention kernel: one warp per point ----------------
// lane owns channels c_i = lane + 32*i (i = head index, i=0..3)
__global__ void __launch_bounds__(256) attn_kernel(const float* __restrict__ xyzs,
                                                   const int* __restrict__ kg,
                                                   const float* __restrict__ A2,
                                                   const float* __restrict__ P1,
                                                   const float* __restrict__ bp1,
                                                   const float* __restrict__ P2,
                                                   const float* __restrict__ bp2) {
    const unsigned FULL = 0xffffffffu;
    const int warp = threadIdx.x >> 5;
    const int lane = threadIdx.x & 31;
    const int pt   = blockIdx.x * 8 + warp;          // < NPTS
    const int bN   = pt & ~(NN - 1);                 // b * N

    // per-lane channel constants for pass 1
    float hbase[4], p2a1c[3][4], A2c[4][4];
#pragma unroll
    for (int i = 0; i < 4; i++) {
        int c = lane + 32 * i;
        hbase[i] = g_QA[(size_t)pt * HD + c] + g_c1[c];
#pragma unroll
        for (int r = 0; r < 3; r++) p2a1c[r][i] = g_P2A1[r * HD + c];
        float4 a2v = *(const float4*)(A2 + c * 4);
        A2c[i][0] = a2v.x; A2c[i][1] = a2v.y; A2c[i][2] = a2v.z; A2c[i][3] = a2v.w;
    }
    float P1r[9];
#pragma unroll
    for (int i = 0; i < 9; i++) P1r[i] = P1[i];
    float bp1r[3] = {bp1[0], bp1[1], bp1[2]};
    const float cx = xyzs[(size_t)pt * 3 + 0];
    const float cy = xyzs[(size_t)pt * 3 + 1];
    const float cz = xyzs[(size_t)pt * 3 + 2];

    int nid[NK];
    float l[4] = {0.f, 0.f, 0.f, 0.f};

    // ---- pass 1: per-neighbor logits ----
#pragma unroll
    for (int k = 0; k < NK; k++) {
        int idx = kg[(size_t)pt * NK + k];
        nid[k] = idx;
        const float* nx = xyzs + (size_t)(bN + idx) * 3;
        float rx = cx - nx[0], ry = cy - nx[1], rz = cz - nx[2];
        float t0 = fmaxf(fmaf(rx, P1r[0], fmaf(ry, P1r[3], fmaf(rz, P1r[6], bp1r[0]))), 0.f);
        float t1 = fmaxf(fmaf(rx, P1r[1], fmaf(ry, P1r[4], fmaf(rz, P1r[7], bp1r[1]))), 0.f);
        float t2 = fmaxf(fmaf(rx, P1r[2], fmaf(ry, P1r[5], fmaf(rz, P1r[8], bp1r[2]))), 0.f);
        const float* karow = g_KA + (size_t)(bN + idx) * HD;
        float p[4] = {0.f, 0.f, 0.f, 0.f};
#pragma unroll
        for (int i = 0; i < 4; i++) {
            float h = hbase[i] - karow[lane + 32 * i];
            h = fmaf(t0, p2a1c[0][i], h);
            h = fmaf(t1, p2a1c[1][i], h);
            h = fmaf(t2, p2a1c[2][i], h);
            float r = fmaxf(h, 0.f);
#pragma unroll
            for (int hh = 0; hh < 4; hh++) p[hh] = fmaf(r, A2c[i][hh], p[hh]);
        }
        // butterfly reduce over 32 lanes
#pragma unroll
        for (int m = 16; m >= 1; m >>= 1) {
#pragma unroll
            for (int hh = 0; hh < 4; hh++) p[hh] += __shfl_xor_sync(FULL, p[hh], m);
        }
        if (lane == k) {
#pragma unroll
            for (int hh = 0; hh < 4; hh++) l[hh] = p[hh];
        }
    }

    // ---- softmax over K (lanes 0..15 hold logits; b2 shift cancels) ----
    float mx[4], e[4], s[4], at[4];
#pragma unroll
    for (int hh = 0; hh < 4; hh++) mx[hh] = l[hh];
#pragma unroll
    for (int m = 8; m >= 1; m >>= 1) {
#pragma unroll
        for (int hh = 0; hh < 4; hh++)
            mx[hh] = fmaxf(mx[hh], __shfl_xor_sync(FULL, mx[hh], m, 16));
    }
#pragma unroll
    for (int hh = 0; hh < 4; hh++) { e[hh] = expf(l[hh] - mx[hh]); s[hh] = e[hh]; }
#pragma unroll
    for (int m = 8; m >= 1; m >>= 1) {
#pragma unroll
        for (int hh = 0; hh < 4; hh++) s[hh] += __shfl_xor_sync(FULL, s[hh], m, 16);
    }
#pragma unroll
    for (int hh = 0; hh < 4; hh++) at[hh] = e[hh] / s[hh];

    // per-lane constants for pass 2 (loaded late to reduce register pressure)
    float p2c[3][4], bp2c[4];
#pragma unroll
    for (int i = 0; i < 4; i++) {
        int c = lane + 32 * i;
#pragma unroll
        for (int r = 0; r < 3; r++) p2c[r][i] = P2[r * HD + c];
        bp2c[i] = bp2[c];
    }

    // ---- pass 2: weighted reduce over neighbors ----
    float accv[4] = {0.f, 0.f, 0.f, 0.f};
#pragma unroll
    for (int k = 0; k < NK; k++) {
        float a[4];
#pragma unroll
        for (int hh = 0; hh < 4; hh++) a[hh] = __shfl_sync(FULL, at[hh], k);
        int idx = nid[k];
        const float* nx = xyzs + (size_t)(bN + idx) * 3;
        float rx = cx - nx[0], ry = cy - nx[1], rz = cz - nx[2];
        float t0 = fmaxf(fmaf(rx, P1r[0], fmaf(ry, P1r[3], fmaf(rz, P1r[6], bp1r[0]))), 0.f);
        float t1 = fmaxf(fmaf(rx, P1r[1], fmaf(ry, P1r[4], fmaf(rz, P1r[7], bp1r[1]))), 0.f);
        float t2 = fmaxf(fmaf(rx, P1r[2], fmaf(ry, P1r[5], fmaf(rz, P1r[8], bp1r[2]))), 0.f);
        const float* vrow = g_V + (size_t)(bN + idx) * HD;
#pragma unroll
        for (int i = 0; i < 4; i++) {
            float pe = fmaf(t0, p2c[0][i], fmaf(t1, p2c[1][i], fmaf(t2, p2c[2][i], bp2c[i])));
            float fv = vrow[lane + 32 * i] + pe;
            accv[i] = fmaf(a[i], fv, accv[i]);
        }
    }
#pragma unroll
    for (int i = 0; i < 4; i++) g_fused[(size_t)pt * HD + lane + 32 * i] = accv[i];
}

// ---------------- launch ----------------------------------------------------
extern "C" void kernel_launch(void* const* d_in, const int* in_sizes, int n_in,
                              void* d_out, int out_size) {
    const float* xyzs     = (const float*)d_in[0];
    const float* features = (const float*)d_in[1];
    const int*   kg       = (const int*)d_in[2];
    // d_in[3]=Wk, [4]=Wv, [5]=Wq, [6]=A1, [7]=b1, [8]=A2, [9]=b2,
    // [10]=P1, [11]=bp1, [12]=P2, [13]=bp2, [14]=Wout, [15]=bout
    const float* Wk   = (const float*)d_in[3];
    const float* Wv   = (const float*)d_in[4];
    const float* Wq   = (const float*)d_in[5];
    const float* A1   = (const float*)d_in[6];
    const float* b1   = (const float*)d_in[7];
    const float* A2   = (const float*)d_in[8];
    const float* P1   = (const float*)d_in[10];
    const float* bp1  = (const float*)d_in[11];
    const float* P2   = (const float*)d_in[12];
    const float* bp2  = (const float*)d_in[13];
    const float* Wout = (const float*)d_in[14];
    const float* bout = (const float*)d_in[15];
    float* out = (float*)d_out;

    float *pWqA1, *pWkA1, *pQA, *pKA, *pV, *pFused;
    cudaGetSymbolAddress((void**)&pWqA1, g_WqA1);
    cudaGetSymbolAddress((void**)&pWkA1, g_WkA1);
    cudaGetSymbolAddress((void**)&pQA,   g_QA);
    cudaGetSymbolAddress((void**)&pKA,   g_KA);
    cudaGetSymbolAddress((void**)&pV,    g_V);
    cudaGetSymbolAddress((void**)&pFused, g_fused);

    setup_kernel<<<130, 128>>>(Wq, Wk, A1, P2, b1, bp2);

    const int gblocks = NPTS / 64;   // 256
    gemm_kernel<CIN><<<gblocks, 256>>>(features, pWqA1, nullptr, pQA);
    gemm_kernel<CIN><<<gblocks, 256>>>(features, pWkA1, nullptr, pKA);
    gemm_kernel<CIN><<<gblocks, 256>>>(features, Wv,    nullptr, pV);

    attn_kernel<<<NPTS / 8, 256>>>(xyzs, kg, A2, P1, bp1, P2, bp2);

    gemm_kernel<HD><<<gblocks, 256>>>(pFused, Wout, bout, out);
}

// round 2
// speedup vs baseline: 1.2604x; 1.2604x over previous
#include <cuda_runtime.h>

#define NB   2
#define NN   8192
#define NK   16
#define NH   4
#define ND   32
#define HD   128
#define CIN  64
#define COUT 128
#define NPTS (NB * NN)   // 16384
#define NCAT 384         // QA|KA|V concatenated

// ---------------- scratch (device globals; no allocations allowed) ----------
__device__ float g_Wcat[CIN * NCAT];   // [WqA1 | WkA1 | Wv]
__device__ float g_P2A1[3 * HD];
__device__ float g_c1[HD];
__device__ float g_QKV[NPTS * NCAT];   // per-point [QA(128) | KA(128) | V(128)]
__device__ float g_fused[NPTS * HD];

// ---------------- weight folding -------------------------------------------
// blocks 0..63: row r of Wcat. block 64: P2A1 (3x128) and c1.
__global__ void setup_kernel(const float* __restrict__ Wq, const float* __restrict__ Wk,
                             const float* __restrict__ Wv, const float* __restrict__ A1,
                             const float* __restrict__ P2, const float* __restrict__ b1,
                             const float* __restrict__ bp2) {
    int c = threadIdx.x;          // 0..383
    int r = blockIdx.x;
    if (r < CIN) {
        float acc;
        if (c < HD) {
            acc = 0.f;
            for (int j = 0; j < HD; j++) acc = fmaf(Wq[r * HD + j], A1[j * HD + c], acc);
        } else if (c < 2 * HD) {
            int cc = c - HD;
            acc = 0.f;
            for (int j = 0; j < HD; j++) acc = fmaf(Wk[r * HD + j], A1[j * HD + cc], acc);
        } else {
            acc = Wv[r * HD + (c - 2 * HD)];
        }
        g_Wcat[r * NCAT + c] = acc;
    } else if (c < HD) {
        for (int rr = 0; rr < 3; rr++) {
            float acc = 0.f;
            for (int j = 0; j < HD; j++) acc = fmaf(P2[rr * HD + j], A1[j * HD + c], acc);
            g_P2A1[rr * HD + c] = acc;
        }
        float acc = b1[c];
        for (int j = 0; j < HD; j++) acc = fmaf(bp2[j], A1[j * HD + c], acc);
        g_c1[c] = acc;
    }
}

// ---------------- tiled fp32 GEMM ------------------------------------------
// C[M x N] = A[M x KD] @ W[KD x N] (+bias). Block: 256 threads (8 warps).
// Tile: MT rows x 128 cols. Warp w owns rows w*RPW..w*RPW+RPW-1 (RPW = MT/8),
// lane owns cols lane+32q (q=0..3). As reads are warp-broadcast, Bs reads are
// lane-consecutive -> zero bank conflicts.
template <int KD, int MT, int LDW, int LDC, bool HASBIAS>
__global__ void __launch_bounds__(256) gemm_kernel(const float* __restrict__ A,
                                                   const float* __restrict__ W,
                                                   const float* __restrict__ bias,
                                                   float* __restrict__ C) {
    constexpr int RPW = MT / 8;
    __shared__ float As[MT][64];
    __shared__ float Bs[64][HD];

    const int tid  = threadIdx.x;
    const int w    = tid >> 5;
    const int lane = tid & 31;
    const int row0 = blockIdx.x * MT;
    const int col0 = blockIdx.y * HD;

    float acc[RPW][4];
#pragma unroll
    for (int r = 0; r < RPW; r++)
#pragma unroll
        for (int q = 0; q < 4; q++) acc[r][q] = 0.f;

#pragma unroll 1
    for (int kk = 0; kk < KD; kk += 64) {
        if (kk) __syncthreads();
        // As: MT x 64 floats, float4 coalesced
#pragma unroll
        for (int i = tid; i < MT * 16; i += 256) {
            int p = i >> 4, q = i & 15;
            *(float4*)&As[p][q * 4] =
                *(const float4*)(A + (size_t)(row0 + p) * KD + kk + q * 4);
        }
        // Bs: 64 x 128
#pragma unroll
        for (int i = tid; i < 64 * 32; i += 256) {
            int j = i >> 5, q = i & 31;
            *(float4*)&Bs[j][q * 4] =
                *(const float4*)(W + (size_t)(kk + j) * LDW + col0 + q * 4);
        }
        __syncthreads();

#pragma unroll 16
        for (int j = 0; j < 64; j++) {
            float b[4];
#pragma unroll
            for (int q = 0; q < 4; q++) b[q] = Bs[j][lane + 32 * q];
#pragma unroll
            for (int r = 0; r < RPW; r++) {
                float a = As[w * RPW + r][j];
#pragma unroll
                for (int q = 0; q < 4; q++) acc[r][q] = fmaf(a, b[q], acc[r][q]);
            }
        }
    }

#pragma unroll
    for (int r = 0; r < RPW; r++) {
        float* crow = C + (size_t)(row0 + w * RPW + r) * LDC + col0;
#pragma unroll
        for (int q = 0; q < 4; q++) {
            float o = acc[r][q];
            if (HASBIAS) o += bias[col0 + lane + 32 * q];
            crow[lane + 32 * q] = o;
        }
    }
}

// ---------------- fused attention kernel: one warp per point ----------------
// lane owns channels c_i = lane + 32*i (i = head index, i=0..3).
__global__ void __launch_bounds__(128) attn_kernel(const float* __restrict__ xyzs,
                                                   const int* __restrict__ kg,
                                                   const float* __restrict__ A2,
                                                   const float* __restrict__ P1,
                                                   const float* __restrict__ bp1,
                                                   const float* __restrict__ P2,
                                                   const float* __restrict__ bp2) {
    const unsigned FULL = 0xffffffffu;
    const int warp = threadIdx.x >> 5;
    const int lane = threadIdx.x & 31;
    const int pt   = blockIdx.x * 4 + warp;
    const int bN   = pt & ~(NN - 1);

    float hbase[4], p2a1c[3][4], A2c[4][4];
#pragma unroll
    for (int i = 0; i < 4; i++) {
        int c = lane + 32 * i;
        hbase[i] = g_QKV[(size_t)pt * NCAT + c] + g_c1[c];
#pragma unroll
        for (int r = 0; r < 3; r++) p2a1c[r][i] = g_P2A1[r * HD + c];
        float4 a2v = *(const float4*)(A2 + c * 4);
        A2c[i][0] = a2v.x; A2c[i][1] = a2v.y; A2c[i][2] = a2v.z; A2c[i][3] = a2v.w;
    }
    float P1r[9];
#pragma unroll
    for (int i = 0; i < 9; i++) P1r[i] = P1[i];
    float bp1r[3] = {bp1[0], bp1[1], bp1[2]};
    const float cx = xyzs[(size_t)pt * 3 + 0];
    const float cy = xyzs[(size_t)pt * 3 + 1];
    const float cz = xyzs[(size_t)pt * 3 + 2];

    // all 16 neighbor indices live distributed: lane l holds kg[pt][l&15]
    const int idx_l = kg[(size_t)pt * NK + (lane & 15)];

    const bool hi = (lane & 16) != 0;
    const bool b3 = (lane & 8) != 0;

    float lk0 = 0.f, lk1 = 0.f;

    // ---- pass 1: per-neighbor logits ----
#pragma unroll
    for (int k = 0; k < NK; k++) {
        int idx = __shfl_sync(FULL, idx_l, k);
        const float* nx = xyzs + (size_t)(bN + idx) * 3;
        float rx = cx - nx[0], ry = cy - nx[1], rz = cz - nx[2];
        float t0 = fmaxf(fmaf(rx, P1r[0], fmaf(ry, P1r[3], fmaf(rz, P1r[6], bp1r[0]))), 0.f);
        float t1 = fmaxf(fmaf(rx, P1r[1], fmaf(ry, P1r[4], fmaf(rz, P1r[7], bp1r[1]))), 0.f);
        float t2 = fmaxf(fmaf(rx, P1r[2], fmaf(ry, P1r[5], fmaf(rz, P1r[8], bp1r[2]))), 0.f);
        const float* karow = g_QKV + (size_t)(bN + idx) * NCAT + HD;
        float p0 = 0.f, p1 = 0.f, p2 = 0.f, p3 = 0.f;
#pragma unroll
        for (int i = 0; i < 4; i++) {
            float h = hbase[i] - karow[lane + 32 * i];
            h = fmaf(t0, p2a1c[0][i], h);
            h = fmaf(t1, p2a1c[1][i], h);
            h = fmaf(t2, p2a1c[2][i], h);
            float r = fmaxf(h, 0.f);
            p0 = fmaf(r, A2c[i][0], p0);
            p1 = fmaf(r, A2c[i][1], p1);
            p2 = fmaf(r, A2c[i][2], p2);
            p3 = fmaf(r, A2c[i][3], p3);
        }
        // split-head reduction: 6 shuffles total
        float sa = hi ? p0 : p2;
        float sb = hi ? p1 : p3;
        float ra = __shfl_xor_sync(FULL, sa, 16);
        float rb = __shfl_xor_sync(FULL, sb, 16);
        float u0 = (hi ? p2 : p0) + ra;
        float u1 = (hi ? p3 : p1) + rb;
        float sc = b3 ? u0 : u1;
        float rc = __shfl_xor_sync(FULL, sc, 8);
        float ww = (b3 ? u1 : u0) + rc;
        ww += __shfl_xor_sync(FULL, ww, 4);
        ww += __shfl_xor_sync(FULL, ww, 2);
        ww += __shfl_xor_sync(FULL, ww, 1);
        // logit(h,k) lands at lane 8h + (k&7); h = lane>>3
        if ((lane & 7) == (k & 7)) {
            if (k < 8) lk0 = ww; else lk1 = ww;
        }
    }

    // ---- softmax: head h lives in 8-lane group [8h, 8h+7], 2 logits/lane ----
    float mx = fmaxf(lk0, lk1);
    mx = fmaxf(mx, __shfl_xor_sync(FULL, mx, 4));
    mx = fmaxf(mx, __shfl_xor_sync(FULL, mx, 2));
    mx = fmaxf(mx, __shfl_xor_sync(FULL, mx, 1));
    float e0 = __expf(lk0 - mx), e1 = __expf(lk1 - mx);
    float s = e0 + e1;
    s += __shfl_xor_sync(FULL, s, 4);
    s += __shfl_xor_sync(FULL, s, 2);
    s += __shfl_xor_sync(FULL, s, 1);
    float inv = __fdividef(1.f, s);
    float a0 = e0 * inv, a1 = e1 * inv;   // attn(h=lane>>3, k=(lane&7)[+8])

    // per-lane constants for pass 2
    float p2c[3][4], bp2c[4];
#pragma unroll
    for (int i = 0; i < 4; i++) {
        int c = lane + 32 * i;
#pragma unroll
        for (int r = 0; r < 3; r++) p2c[r][i] = P2[r * HD + c];
        bp2c[i] = bp2[c];
    }

    // ---- pass 2: weighted reduce over neighbors ----
    float accv[4] = {0.f, 0.f, 0.f, 0.f};
#pragma unroll
    for (int k = 0; k < NK; k++) {
        float asel = (k < 8) ? a0 : a1;
        float aw[4];
#pragma unroll
        for (int i = 0; i < 4; i++) aw[i] = __shfl_sync(FULL, asel, 8 * i + (k & 7));
        int idx = __shfl_sync(FULL, idx_l, k);
        const float* nx = xyzs + (size_t)(bN + idx) * 3;
        float rx = cx - nx[0], ry = cy - nx[1], rz = cz - nx[2];
        float t0 = fmaxf(fmaf(rx, P1r[0], fmaf(ry, P1r[3], fmaf(rz, P1r[6], bp1r[0]))), 0.f);
        float t1 = fmaxf(fmaf(rx, P1r[1], fmaf(ry, P1r[4], fmaf(rz, P1r[7], bp1r[1]))), 0.f);
        float t2 = fmaxf(fmaf(rx, P1r[2], fmaf(ry, P1r[5], fmaf(rz, P1r[8], bp1r[2]))), 0.f);
        const float* vrow = g_QKV + (size_t)(bN + idx) * NCAT + 2 * HD;
#pragma unroll
        for (int i = 0; i < 4; i++) {
            float pe = fmaf(t0, p2c[0][i], fmaf(t1, p2c[1][i], fmaf(t2, p2c[2][i], bp2c[i])));
            float fv = vrow[lane + 32 * i] + pe;
            accv[i] = fmaf(aw[i], fv, accv[i]);
        }
    }
#pragma unroll
    for (int i = 0; i < 4; i++) g_fused[(size_t)pt * HD + lane + 32 * i] = accv[i];
}

// ---------------- launch ----------------------------------------------------
extern "C" void kernel_launch(void* const* d_in, const int* in_sizes, int n_in,
                              void* d_out, int out_size) {
    const float* xyzs     = (const float*)d_in[0];
    const float* features = (const float*)d_in[1];
    const int*   kg       = (const int*)d_in[2];
    const float* Wk   = (const float*)d_in[3];
    const float* Wv   = (const float*)d_in[4];
    const float* Wq   = (const float*)d_in[5];
    const float* A1   = (const float*)d_in[6];
    const float* b1   = (const float*)d_in[7];
    const float* A2   = (const float*)d_in[8];
    const float* P1   = (const float*)d_in[10];
    const float* bp1  = (const float*)d_in[11];
    const float* P2   = (const float*)d_in[12];
    const float* bp2  = (const float*)d_in[13];
    const float* Wout = (const float*)d_in[14];
    const float* bout = (const float*)d_in[15];
    float* out = (float*)d_out;

    float *pWcat, *pQKV, *pFused;
    cudaGetSymbolAddress((void**)&pWcat,  g_Wcat);
    cudaGetSymbolAddress((void**)&pQKV,   g_QKV);
    cudaGetSymbolAddress((void**)&pFused, g_fused);

    setup_kernel<<<CIN + 1, NCAT>>>(Wq, Wk, Wv, A1, P2, b1, bp2);

    // QA|KA|V in one GEMM: [16384 x 64] @ [64 x 384]
    gemm_kernel<CIN, 64, NCAT, NCAT, false>
        <<<dim3(NPTS / 64, 3), 256>>>(features, pWcat, nullptr, pQKV);

    attn_kernel<<<NPTS / 4, 128>>>(xyzs, kg, A2, P1, bp1, P2, bp2);

    // out = fused @ Wout + bout : [16384 x 128] @ [128 x 128]
    gemm_kernel<HD, 32, HD, HD, true>
        <<<dim3(NPTS / 32, 1), 256>>>(pFused, Wout, bout, out);
}